// round 2
// baseline (speedup 1.0000x reference)
#include <cuda_runtime.h>
#include <cuda_bf16.h>

// Fixed shapes: B=1, N=1000, T=256, D=512, M=258, NUM=10
// out row = 6*512 + 10 = 3082 floats (12328 B -> 16B-aligned only for even n)
#define N_CAND 1000
#define T_DIM 256
#define D_DIM 512
#define M_DIM 258
#define NUMF 10
#define ROW_OUT (6 * D_DIM + NUMF)   // 3082

// One block per candidate, 256 threads.
// Threads split into two halves of 128 lanes; each half copies 3 of the 6
// 512-float sections with float4 loads (source rows are 2048B-aligned).
//   half 0: sections 0 (blo[c1]), 2 (blo[c4]), 4 (att[c0+2])
//   half 1: sections 1 (blo[c2]), 3 (blo[c5]), 5 (att[c3+2])
// Stores: float4 when the output row is 16B-aligned (even n), else 2x float2.
__global__ __launch_bounds__(256) void feature_gather_kernel(
    const int* __restrict__ cand,        // [N,6]
    const float* __restrict__ num,       // [N,10]
    const float* __restrict__ blo,       // [N,T,D]
    const float* __restrict__ att,       // [N,M,D]
    float* __restrict__ out)             // [N,3082]
{
    const int n = blockIdx.x;
    const int t = threadIdx.x;
    const int half = t >> 7;       // 0 or 1
    const int lane = t & 127;      // 0..127  (float4 lane within a section)

    // Candidate indices: 24B row, always 8B-aligned -> three int2 loads.
    const int2* cp = (const int2*)(cand + n * 6);
    const int2 p01 = cp[0];        // c0, c1
    const int2 p23 = cp[1];        // c2, c3
    const int2 p45 = cp[2];        // c4, c5

    const float4* b4 = (const float4*)(blo + (size_t)n * T_DIM * D_DIM);
    const float4* a4 = (const float4*)(att + (size_t)n * M_DIM * D_DIM);
    const int R4 = D_DIM / 4;      // 128 float4 per row

    const int rowA = half ? p23.x : p01.y;          // c2 : c1      (blo)
    const int rowB = half ? p45.y : p45.x;          // c5 : c4      (blo)
    const int rowC = (half ? p23.y : p01.x) + 2;    // c3+2 : c0+2  (att)

    // Issue all three 16B loads before any store (MLP=3).
    const float4 vA = b4[(size_t)rowA * R4 + lane];
    const float4 vB = b4[(size_t)rowB * R4 + lane];
    const float4 vC = a4[(size_t)rowC * R4 + lane];

    float* outRow = out + (size_t)n * ROW_OUT;
    // Destination section ids: sA = half, sB = half+2, sC = half+4.
    if ((n & 1) == 0) {
        float4* o4 = (float4*)outRow;                 // 16B-aligned row
        o4[(half + 0) * R4 + lane] = vA;
        o4[(half + 2) * R4 + lane] = vB;
        o4[(half + 4) * R4 + lane] = vC;
    } else {
        float2* o2 = (float2*)outRow;                 // 8B-aligned row
        const int iA = ((half + 0) * R4 + lane) * 2;
        const int iB = ((half + 2) * R4 + lane) * 2;
        const int iC = ((half + 4) * R4 + lane) * 2;
        o2[iA]     = make_float2(vA.x, vA.y);
        o2[iA + 1] = make_float2(vA.z, vA.w);
        o2[iB]     = make_float2(vB.x, vB.y);
        o2[iB + 1] = make_float2(vB.z, vB.w);
        o2[iC]     = make_float2(vC.x, vC.y);
        o2[iC + 1] = make_float2(vC.z, vC.w);
    }

    // Numeric features: 10 floats = 5 float2 (both src and dst 8B-aligned).
    if (t < NUMF / 2) {
        const float2* num2 = (const float2*)(num + (size_t)n * NUMF);
        ((float2*)outRow)[6 * (D_DIM / 2) + t] = num2[t];
    }
}

extern "C" void kernel_launch(void* const* d_in, const int* in_sizes, int n_in,
                              void* d_out, int out_size) {
    const int*   cand = (const int*)d_in[0];
    const float* num  = (const float*)d_in[1];
    const float* blo  = (const float*)d_in[2];
    const float* att  = (const float*)d_in[3];
    float* out = (float*)d_out;

    feature_gather_kernel<<<N_CAND, 256>>>(cand, num, blo, att, out);
}